// round 11
// baseline (speedup 1.0000x reference)
#include <cuda_runtime.h>
#include <math.h>

#define N_NODES  100000
#define N_EDGES  400000
#define N_GRAPHS 4000
#define D        70
#define NP       240
#define KDIM     280
#define BCAP     32           // bucket capacity (P(deg>32) ~ e^-44 for Poisson(4))
#define NPAD     100032       // padded rows (1563 * 64)

// ---------------- scratch (device globals) ---------------------------------
__device__ float g_h[N_NODES * D];
// agg in pair-permuted tf32 layout: value of logical k stored at posk(k) within
// each 280-float row; rows >= N_NODES stay zero (device globals zero-init).
__device__ __align__(16) float g_agg[NPAD * KDIM];
__device__ float g_amp[N_NODES];
__device__ int   g_cnt[N_NODES];
__device__ int2  g_bucket[N_NODES * BCAP];    // (edge id, src node)
__device__ float g_gsum[N_GRAPHS * D];
__device__ float g_gcnt[N_GRAPHS];
// packed tf32 weights: [layer][stage(35)][1920 floats]  (see init_kernel)
__device__ __align__(16) float g_w3[4 * KDIM * NP];

__constant__ int c_atom_off[9] = {0, 119, 124, 136, 148, 158, 164, 170, 172};

#define AVG_LOG_F 1.2465355243460002f
#define INV_BN    0.9999950000374997f

__device__ __forceinline__ float to_tf32(float x) {
    unsigned u;
    asm("cvt.rna.tf32.f32 %0, %1;" : "=r"(u) : "f"(x));
    return __uint_as_float(u);
}

// position of logical k inside its 8-group after pair permutation
__device__ __forceinline__ int posk(int k) {
    return (k & ~7) | (((k & 3) << 1) | ((k >> 2) & 1));
}

__device__ __forceinline__ void mma_tf32(float c[4], unsigned a0, unsigned a1,
                                         unsigned a2, unsigned a3,
                                         unsigned b0, unsigned b1) {
    asm volatile(
        "mma.sync.aligned.m16n8k8.row.col.f32.tf32.tf32.f32 "
        "{%0,%1,%2,%3}, {%4,%5,%6,%7}, {%8,%9}, {%0,%1,%2,%3};\n"
        : "+f"(c[0]), "+f"(c[1]), "+f"(c[2]), "+f"(c[3])
        : "r"(a0), "r"(a1), "r"(a2), "r"(a3), "r"(b0), "r"(b1));
}

#define CP16(dst, src) \
    asm volatile("cp.async.cg.shared.global [%0], [%1], 16;\n" :: "r"(dst), "l"(src))
#define CP8(dst, src) \
    asm volatile("cp.async.ca.shared.global [%0], [%1], 8;\n" :: "r"(dst), "l"(src))
#define CPCOMMIT() asm volatile("cp.async.commit_group;\n" ::: "memory")
#define CPWAIT(n)  asm volatile("cp.async.wait_group %0;\n" :: "n"(n) : "memory")

__device__ __forceinline__ unsigned smem_u32(const void* p) {
    return (unsigned)__cvta_generic_to_shared(p);
}
__device__ __forceinline__ float4 lds128(unsigned a) {
    float4 v;
    asm volatile("ld.shared.v4.f32 {%0,%1,%2,%3}, [%4];"
                 : "=f"(v.x), "=f"(v.y), "=f"(v.z), "=f"(v.w) : "r"(a));
    return v;
}
__device__ __forceinline__ float2 lds64(unsigned a) {
    float2 v;
    asm volatile("ld.shared.v2.f32 {%0,%1}, [%2];" : "=f"(v.x), "=f"(v.y) : "r"(a));
    return v;
}
#define FU(x) __float_as_uint(x)

// ------- launch 1: atom encoder + zero init + W3 pack (all independent) ----
__global__ void init_kernel(const int* __restrict__ x, const float* __restrict__ emb,
                            const float* __restrict__ W) {
    int flat = threadIdx.y * 70 + threadIdx.x;
    int gtid = blockIdx.x * 280 + flat;
    if (gtid < N_NODES) g_cnt[gtid] = 0;
    if (gtid < N_GRAPHS * D) g_gsum[gtid] = 0.f;
    if (gtid < N_GRAPHS) g_gcnt[gtid] = 0.f;

    // W3 pack into tile-paired tf32 layout (one float per thread)
    if (gtid < 268800) {                      // 4 layers * 35 stages * 1920
        int layer = gtid / 67200;
        int rem = gtid - layer * 67200;
        int st = rem / 1920;
        int f = rem - st * 1920;
        int l, r4, h, dk, col;
        if (f < 1792) {
            int q = f >> 2, comp = f & 3;
            l = q & 3; r4 = (q >> 2) & 7;
            int rest = q >> 5;
            int p = rest % 7; h = rest / 7;
            col = h * 120 + p * 16 + r4 + ((comp >> 1) ? 8 : 0);
            dk = (comp & 1) ? 4 : 0;
        } else {
            int m = f - 1792;
            int f2 = m >> 1, c2 = m & 1;
            l = f2 & 3; r4 = (f2 >> 2) & 7; h = f2 >> 5;
            col = h * 120 + 112 + r4;
            dk = c2 ? 4 : 0;
        }
        int kk = st * 8 + l + dk;
        int cr = col - h * 120;
        int tile = cr >> 3, u = cr & 7;
        int panel = tile / 5, jb = tile - panel * 5;
        int j = h * 40 + jb * 8 + u;
        float v = 0.f;
        if (j < 70)
            v = to_tf32(W[((size_t)layer * 840 + panel * KDIM + kk) * 70 + j]);
        g_w3[gtid] = v;
    }

    int n = blockIdx.x * blockDim.y + threadIdx.y;
    int f = threadIdx.x;
    if (n >= N_NODES) return;
    float s = 0.f;
#pragma unroll
    for (int j = 0; j < 9; j++) {
        int idx = x[n * 9 + j] + c_atom_off[j];
        s += emb[idx * D + f];
    }
    g_h[n * D + f] = s;
}

// ------- launch 2: direct bucket scatter -----------------------------------
__global__ void scatter_kernel(const int* __restrict__ ei) {
    int e = blockIdx.x * blockDim.x + threadIdx.x;
    if (e < N_EDGES) {
        int d = ei[N_EDGES + e];
        int s = ei[e];
        int p = atomicAdd(&g_cnt[d], 1);
        if (p < BCAP) g_bucket[(size_t)d * BCAP + p] = make_int2(e, s);
    }
}

// ------- per-node aggregation (one warp per node, 4 edges in flight) -------
__global__ void agg_kernel(const float* __restrict__ ea) {
    int gtid = blockIdx.x * blockDim.x + threadIdx.x;
    int node = gtid >> 5;
    int lane = gtid & 31;
    if (node >= N_NODES) return;

    const float2* hrow = (const float2*)(g_h + (size_t)node * D);
    float2 hm = hrow[lane];
    float2 ht = make_float2(0.f, 0.f);
    if (lane < 3) ht = hrow[32 + lane];

    int cnt0 = g_cnt[node];
    int cnt = (cnt0 < BCAP) ? cnt0 : BCAP;

    // each lane holds one bucket slot; broadcast via shfl
    int2 myes = make_int2(0, 0);
    if (lane < cnt) myes = g_bucket[(size_t)node * BCAP + lane];

    float2 s  = make_float2(0.f, 0.f), q  = make_float2(0.f, 0.f);
    float2 mn = make_float2(3.4e38f, 3.4e38f), mx = make_float2(0.f, 0.f);
    float2 st = make_float2(0.f, 0.f), qt = make_float2(0.f, 0.f);
    float2 mnt = make_float2(3.4e38f, 3.4e38f), mxt = make_float2(0.f, 0.f);

    for (int p = 0; p < cnt; p += 4) {
        // clamped indices -> unconditional loads (max MLP), guarded accumulate
        int pj0 = p,                        pj1 = (p + 1 < cnt) ? p + 1 : cnt - 1;
        int pj2 = (p + 2 < cnt) ? p + 2 : cnt - 1, pj3 = (p + 3 < cnt) ? p + 3 : cnt - 1;
        int e0 = __shfl_sync(0xffffffffu, myes.x, pj0), s0 = __shfl_sync(0xffffffffu, myes.y, pj0);
        int e1 = __shfl_sync(0xffffffffu, myes.x, pj1), s1 = __shfl_sync(0xffffffffu, myes.y, pj1);
        int e2 = __shfl_sync(0xffffffffu, myes.x, pj2), s2 = __shfl_sync(0xffffffffu, myes.y, pj2);
        int e3 = __shfl_sync(0xffffffffu, myes.x, pj3), s3 = __shfl_sync(0xffffffffu, myes.y, pj3);

        const float2* hs0 = (const float2*)(g_h + (size_t)s0 * D);
        const float2* hs1 = (const float2*)(g_h + (size_t)s1 * D);
        const float2* hs2 = (const float2*)(g_h + (size_t)s2 * D);
        const float2* hs3 = (const float2*)(g_h + (size_t)s3 * D);
        const float2* er0 = (const float2*)(ea + (size_t)e0 * D);
        const float2* er1 = (const float2*)(ea + (size_t)e1 * D);
        const float2* er2 = (const float2*)(ea + (size_t)e2 * D);
        const float2* er3 = (const float2*)(ea + (size_t)e3 * D);

        float2 a0 = hs0[lane], b0 = er0[lane];
        float2 a1 = hs1[lane], b1 = er1[lane];
        float2 a2 = hs2[lane], b2 = er2[lane];
        float2 a3 = hs3[lane], b3 = er3[lane];

        float2 at0, bt0, at1, bt1, at2, bt2, at3, bt3;
        if (lane < 3) {
            at0 = hs0[32 + lane]; bt0 = er0[32 + lane];
            at1 = hs1[32 + lane]; bt1 = er1[32 + lane];
            at2 = hs2[32 + lane]; bt2 = er2[32 + lane];
            at3 = hs3[32 + lane]; bt3 = er3[32 + lane];
        }

#define ACC_MAIN(aj, bj, cond)                                                  \
        if (cond) {                                                             \
            float m0 = fmaxf(hm.x + (aj).x + (bj).x, 0.f);                      \
            float m1 = fmaxf(hm.y + (aj).y + (bj).y, 0.f);                      \
            s.x += m0; q.x += m0 * m0; mn.x = fminf(mn.x, m0); mx.x = fmaxf(mx.x, m0); \
            s.y += m1; q.y += m1 * m1; mn.y = fminf(mn.y, m1); mx.y = fmaxf(mx.y, m1); \
        }
#define ACC_TAIL(aj, bj, cond)                                                  \
        if (cond) {                                                             \
            float t0 = fmaxf(ht.x + (aj).x + (bj).x, 0.f);                      \
            float t1 = fmaxf(ht.y + (aj).y + (bj).y, 0.f);                      \
            st.x += t0; qt.x += t0 * t0; mnt.x = fminf(mnt.x, t0); mxt.x = fmaxf(mxt.x, t0); \
            st.y += t1; qt.y += t1 * t1; mnt.y = fminf(mnt.y, t1); mxt.y = fmaxf(mxt.y, t1); \
        }
        ACC_MAIN(a0, b0, true)
        ACC_MAIN(a1, b1, p + 1 < cnt)
        ACC_MAIN(a2, b2, p + 2 < cnt)
        ACC_MAIN(a3, b3, p + 3 < cnt)
        if (lane < 3) {
            ACC_TAIL(at0, bt0, true)
            ACC_TAIL(at1, bt1, p + 1 < cnt)
            ACC_TAIL(at2, bt2, p + 2 < cnt)
            ACC_TAIL(at3, bt3, p + 3 < cnt)
        }
#undef ACC_MAIN
#undef ACC_TAIL
    }
    float cf = (cnt > 0) ? (float)cnt : 1.f;
    float inv = 1.f / cf;

    float2 me = make_float2(s.x * inv, s.y * inv);
    float2 sd;
    sd.x = sqrtf(fmaxf(q.x * inv - me.x * me.x, 0.f) + 1e-5f);
    sd.y = sqrtf(fmaxf(q.y * inv - me.y * me.y, 0.f) + 1e-5f);
    float2 met = make_float2(st.x * inv, st.y * inv);
    float2 sdt;
    sdt.x = sqrtf(fmaxf(qt.x * inv - met.x * met.x, 0.f) + 1e-5f);
    sdt.y = sqrtf(fmaxf(qt.y * inv - met.y * met.y, 0.f) + 1e-5f);
    if (cnt == 0) {
        mn = make_float2(0.f, 0.f); mx = make_float2(0.f, 0.f);
        mnt = make_float2(0.f, 0.f); mxt = make_float2(0.f, 0.f);
    }

    // permuted tf32 stores: logical k = stat*70 + feat -> row offset posk(k)
    float* arow = g_agg + (size_t)node * KDIM;
    int f0 = 2 * lane;
    arow[posk(f0)]            = to_tf32(me.x);  arow[posk(f0 + 1)]            = to_tf32(me.y);
    arow[posk(70 + f0)]       = to_tf32(mn.x);  arow[posk(70 + f0 + 1)]       = to_tf32(mn.y);
    arow[posk(140 + f0)]      = to_tf32(mx.x);  arow[posk(140 + f0 + 1)]      = to_tf32(mx.y);
    arow[posk(210 + f0)]      = to_tf32(sd.x);  arow[posk(210 + f0 + 1)]      = to_tf32(sd.y);
    if (lane < 3) {
        int ft = 64 + 2 * lane;
        arow[posk(ft)]        = to_tf32(met.x); arow[posk(ft + 1)]        = to_tf32(met.y);
        arow[posk(70 + ft)]   = to_tf32(mnt.x); arow[posk(70 + ft + 1)]   = to_tf32(mnt.y);
        arow[posk(140 + ft)]  = to_tf32(mxt.x); arow[posk(140 + ft + 1)]  = to_tf32(mxt.y);
        arow[posk(210 + ft)]  = to_tf32(sdt.x); arow[posk(210 + ft + 1)]  = to_tf32(sdt.y);
    }
    if (lane == 0) g_amp[node] = logf(cf + 1.f) / AVG_LOG_F;
}

// ---------------- TF32 tensor-core GEMM, 1-barrier pipelined ---------------
// [64 x 280] @ [280 x 240]; 8 warps 4m x 2n. All fill addresses precomputed.
#define GM 64
__global__ __launch_bounds__(256, 2)
void gemm_kernel(int layer,
                 const float* __restrict__ b,
                 const float* __restrict__ gamma, const float* __restrict__ beta) {
    __shared__ __align__(16) float4 Asm[2][640];   // [kt&1]: ((g*4+rt)*8+row8)*4+l
    __shared__ __align__(16) float4 Bsm[3][480];   // [s%3]: stage block (1920 floats)
    int t = threadIdx.x;
    int lane = t & 31, wid = t >> 5;
    int wm = wid & 3, wn = wid >> 2;
    int row0 = blockIdx.x * GM;

    unsigned ab0 = smem_u32(&Asm[0][0]), ab1 = smem_u32(&Asm[1][0]);
    unsigned bb0 = smem_u32(&Bsm[0][0]), bb1 = smem_u32(&Bsm[1][0]), bb2 = smem_u32(&Bsm[2][0]);

    float c[15][4];
#pragma unroll
    for (int i = 0; i < 15; i++)
#pragma unroll
        for (int r = 0; r < 4; r++) c[i][r] = 0.f;

    // ---- precomputed fill addressing -------------------------------------
    // A: 1280 CP8 per kt; thread handles idx = t + i*256, i=0..4.
    unsigned a_dst[5];
    const char* a_src[5];
#pragma unroll
    for (int i = 0; i < 5; i++) {
        int idx = t + i * 256;
        int f4i = idx >> 1, hf = idx & 1;
        int l = f4i & 3, row8 = (f4i >> 2) & 7, rt = (f4i >> 5) & 3, g = f4i >> 7;
        int r = rt * 16 + row8 + hf * 8;
        a_dst[i] = (unsigned)(f4i * 16 + hf * 8);
        a_src[i] = (const char*)(g_agg + (size_t)(row0 + r) * KDIM + g * 8 + 2 * l);
    }
    // B: 480 CP16 per stage; thread handles t, and t+256 only when t < 224.
    const bool b2nd = (t < 224);
    const char* b_src = (const char*)((const float4*)g_w3 + (size_t)layer * 16800) + (t << 4);
    unsigned b_dst = (unsigned)(t << 4);

#define ISSUE_A(ktv, base) {                                                   \
        int ko = (ktv) * 160;                                                  \
        CP8((base) + a_dst[0], a_src[0] + ko);                                 \
        CP8((base) + a_dst[1], a_src[1] + ko);                                 \
        CP8((base) + a_dst[2], a_src[2] + ko);                                 \
        CP8((base) + a_dst[3], a_src[3] + ko);                                 \
        CP8((base) + a_dst[4], a_src[4] + ko);                                 \
    }
#define ISSUE_B(sv, base) {                                                    \
        const char* bs = b_src + (size_t)(sv) * 7680;                          \
        CP16((base) + b_dst, bs);                                              \
        if (b2nd) CP16((base) + b_dst + 4096, bs + 4096);                      \
    }

    // per-lane fragment offsets
    unsigned aoff  = ((wm * 8 + (lane >> 2)) * 4 + (lane & 3)) * 16;
    unsigned boffp = wn * 3584 + (lane >> 2) * 64 + (lane & 3) * 16;
    unsigned bofft = 7168 + wn * 256 + (lane >> 2) * 32 + (lane & 3) * 8;

    // prologue
    ISSUE_A(0, ab0); ISSUE_B(0, bb0); CPCOMMIT();
    ISSUE_B(1, bb1); CPCOMMIT();

    unsigned acur = ab0;
    unsigned bprev = bb2, bcur = bb0, bnext = bb1;
    int gg = 0, kt = 0;

    for (int s = 0; s < 35; s++) {
        if (s < 34) { CPWAIT(1); } else { CPWAIT(0); }
        __syncthreads();

        if (s < 33) {
            ISSUE_B(s + 2, bprev);
            if (gg == 3) ISSUE_A(kt + 1, (kt & 1) ? ab0 : ab1);   // (kt+1)&1 buffer
            CPCOMMIT();
        }

        float4 Av = lds128(acur + aoff + (gg << 11));
        unsigned a0 = FU(Av.x), a2 = FU(Av.y), a1 = FU(Av.z), a3 = FU(Av.w);
        unsigned bbase = bcur + boffp;
#pragma unroll
        for (int p = 0; p < 7; p++) {
            float4 Bv = lds128(bbase + p * 512);
            mma_tf32(c[2 * p],     a0, a1, a2, a3, FU(Bv.x), FU(Bv.y));
            mma_tf32(c[2 * p + 1], a0, a1, a2, a3, FU(Bv.z), FU(Bv.w));
        }
        float2 Bt = lds64(bcur + bofft);
        mma_tf32(c[14], a0, a1, a2, a3, FU(Bt.x), FU(Bt.y));

        unsigned tmp = bprev; bprev = bcur; bcur = bnext; bnext = tmp;
        if (++gg == 5) { gg = 0; ++kt; acur = (kt & 1) ? ab1 : ab0; }
    }

    // epilogue: combine 3 panels with amp, bias, BN, relu, residual
    int r0 = row0 + wm * 16 + (lane >> 2);
    int r1 = r0 + 8;
    float amp0 = (r0 < N_NODES) ? g_amp[r0] : 1.f;
    float amp1 = (r1 < N_NODES) ? g_amp[r1] : 1.f;
#pragma unroll
    for (int jb = 0; jb < 5; jb++) {
#pragma unroll
        for (int cc = 0; cc < 2; cc++) {
            int j = wn * 40 + jb * 8 + (lane & 3) * 2 + cc;
            if (j < 70) {
                float bj = b[j], gj = gamma[j], btj = beta[j];
                if (r0 < N_NODES) {
                    float comb = c[jb][cc] + amp0 * c[5 + jb][cc] + c[10 + jb][cc] / amp0;
                    float hn = fmaxf((comb + bj) * INV_BN * gj + btj, 0.f);
                    g_h[(size_t)r0 * D + j] += hn;
                }
                if (r1 < N_NODES) {
                    float comb = c[jb][2 + cc] + amp1 * c[5 + jb][2 + cc] + c[10 + jb][2 + cc] / amp1;
                    float hn = fmaxf((comb + bj) * INV_BN * gj + btj, 0.f);
                    g_h[(size_t)r1 * D + j] += hn;
                }
            }
        }
    }
#undef ISSUE_A
#undef ISSUE_B
}

// ---------------- global mean pool (run-length accumulation) ---------------
#define PNODES 64
__global__ void pool_kernel(const int* __restrict__ batch) {
    int grp = blockIdx.x * blockDim.y + threadIdx.y;
    int f = threadIdx.x;                    // 0..69
    int n0 = grp * PNODES;
    if (n0 >= N_NODES) return;
    int nend = n0 + PNODES; if (nend > N_NODES) nend = N_NODES;
    int curg = batch[n0];
    float acc = 0.f, cacc = 0.f;
    for (int n = n0; n < nend; n++) {
        int gi = batch[n];
        if (gi != curg) {
            atomicAdd(&g_gsum[curg * D + f], acc);
            if (f == 0) atomicAdd(&g_gcnt[curg], cacc);
            curg = gi; acc = 0.f; cacc = 0.f;
        }
        acc += g_h[(size_t)n * D + f];
        cacc += 1.f;
    }
    atomicAdd(&g_gsum[curg * D + f], acc);
    if (f == 0) atomicAdd(&g_gcnt[curg], cacc);
}

// ---------------- final MLP 70->35->17->1 ----------------------------------
__global__ void mlp_kernel(const float* __restrict__ w1, const float* __restrict__ b1,
                           const float* __restrict__ w2, const float* __restrict__ b2,
                           const float* __restrict__ w3, const float* __restrict__ b3,
                           float* __restrict__ out) {
    __shared__ float sg[70], t1[35], t2[17];
    int gi = blockIdx.x;
    int t = threadIdx.x;
    if (t < 70) {
        float cdenom = fmaxf(g_gcnt[gi], 1.f);
        sg[t] = g_gsum[gi * D + t] / cdenom;
    }
    __syncthreads();
    if (t < 35) {
        float s = b1[t];
        for (int k = 0; k < 70; k++) s += sg[k] * w1[k * 35 + t];
        t1[t] = fmaxf(s, 0.f);
    }
    __syncthreads();
    if (t < 17) {
        float s = b2[t];
        for (int k = 0; k < 35; k++) s += t1[k] * w2[k * 17 + t];
        t2[t] = fmaxf(s, 0.f);
    }
    __syncthreads();
    if (t == 0) {
        float s = b3[0];
        for (int k = 0; k < 17; k++) s += t2[k] * w3[k];
        out[gi] = s;
    }
}

// ---------------- launcher --------------------------------------------------
extern "C" void kernel_launch(void* const* d_in, const int* in_sizes, int n_in,
                              void* d_out, int out_size) {
    const int*   x      = (const int*)d_in[0];
    const int*   ei     = (const int*)d_in[1];
    const float* ea     = (const float*)d_in[2];
    const int*   batch  = (const int*)d_in[3];
    const float* emb    = (const float*)d_in[4];
    const float* post_w = (const float*)d_in[5];
    const float* post_b = (const float*)d_in[6];
    const float* gamma  = (const float*)d_in[7];
    const float* beta   = (const float*)d_in[8];
    const float* w1 = (const float*)d_in[9];
    const float* b1 = (const float*)d_in[10];
    const float* w2 = (const float*)d_in[11];
    const float* b2 = (const float*)d_in[12];
    const float* w3 = (const float*)d_in[13];
    const float* b3 = (const float*)d_in[14];
    float* out = (float*)d_out;

    init_kernel<<<(N_NODES + 3) / 4, dim3(70, 4)>>>(x, emb, post_w);   // 1
    scatter_kernel<<<(N_EDGES + 255) / 256, 256>>>(ei);                // 2

    for (int l = 0; l < 4; l++) {
        agg_kernel<<<(N_NODES * 32 + 255) / 256, 256>>>(ea);           // 3 (l=0)
        gemm_kernel<<<NPAD / GM, 256>>>(                               // 4 (l=0) <- profiled
            l, post_b + l * 70, gamma + l * 70, beta + l * 70);
    }

    pool_kernel<<<(1563 + 3) / 4, dim3(70, 4)>>>(batch);
    mlp_kernel<<<N_GRAPHS, 70>>>(w1, b1, w2, b2, w3, b3, out);
}

// round 14
// speedup vs baseline: 1.0925x; 1.0925x over previous
#include <cuda_runtime.h>
#include <math.h>

#define N_NODES  100000
#define N_EDGES  400000
#define N_GRAPHS 4000
#define D        70
#define NP       240
#define KDIM     280
#define BCAP     32           // bucket capacity (P(deg>32) ~ e^-44 for Poisson(4))
#define NPAD     100032       // padded rows (1563 * 64)

// ---------------- scratch (device globals) ---------------------------------
__device__ float g_h[N_NODES * D];
// agg in pair-permuted tf32 layout: value of logical k stored at posk(k) within
// each 280-float row; rows >= N_NODES stay zero (device globals zero-init).
__device__ __align__(16) float g_agg[NPAD * KDIM];
__device__ float g_amp[N_NODES];
__device__ int   g_cnt[N_NODES];
__device__ int2  g_bucket[N_NODES * BCAP];    // (edge id, src node)
__device__ float g_gsum[N_GRAPHS * D];
__device__ float g_gcnt[N_GRAPHS];
// packed tf32 weights: [layer][stage(35)][1920 floats]  (see init_kernel)
__device__ __align__(16) float g_w3[4 * KDIM * NP];

__constant__ int c_atom_off[9] = {0, 119, 124, 136, 148, 158, 164, 170, 172};

#define AVG_LOG_F 1.2465355243460002f
#define INV_BN    0.9999950000374997f

__device__ __forceinline__ float to_tf32(float x) {
    unsigned u;
    asm("cvt.rna.tf32.f32 %0, %1;" : "=r"(u) : "f"(x));
    return __uint_as_float(u);
}

// position of logical k inside its 8-group after pair permutation
__device__ __forceinline__ int posk(int k) {
    return (k & ~7) | (((k & 3) << 1) | ((k >> 2) & 1));
}

__device__ __forceinline__ void mma_tf32(float c[4], unsigned a0, unsigned a1,
                                         unsigned a2, unsigned a3,
                                         unsigned b0, unsigned b1) {
    asm volatile(
        "mma.sync.aligned.m16n8k8.row.col.f32.tf32.tf32.f32 "
        "{%0,%1,%2,%3}, {%4,%5,%6,%7}, {%8,%9}, {%0,%1,%2,%3};\n"
        : "+f"(c[0]), "+f"(c[1]), "+f"(c[2]), "+f"(c[3])
        : "r"(a0), "r"(a1), "r"(a2), "r"(a3), "r"(b0), "r"(b1));
}

#define CP16(dst, src) \
    asm volatile("cp.async.cg.shared.global [%0], [%1], 16;\n" :: "r"(dst), "l"(src))
#define CP8(dst, src) \
    asm volatile("cp.async.ca.shared.global [%0], [%1], 8;\n" :: "r"(dst), "l"(src))
#define CPCOMMIT() asm volatile("cp.async.commit_group;\n" ::: "memory")
#define CPWAIT(n)  asm volatile("cp.async.wait_group %0;\n" :: "n"(n) : "memory")

__device__ __forceinline__ unsigned smem_u32(const void* p) {
    return (unsigned)__cvta_generic_to_shared(p);
}
__device__ __forceinline__ float4 lds128(unsigned a) {
    float4 v;
    asm volatile("ld.shared.v4.f32 {%0,%1,%2,%3}, [%4];"
                 : "=f"(v.x), "=f"(v.y), "=f"(v.z), "=f"(v.w) : "r"(a));
    return v;
}
__device__ __forceinline__ float2 lds64(unsigned a) {
    float2 v;
    asm volatile("ld.shared.v2.f32 {%0,%1}, [%2];" : "=f"(v.x), "=f"(v.y) : "r"(a));
    return v;
}
#define FU(x) __float_as_uint(x)

// ------- launch 1: atom encoder + zero init + W3 pack (all independent) ----
__global__ void init_kernel(const int* __restrict__ x, const float* __restrict__ emb,
                            const float* __restrict__ W) {
    int flat = threadIdx.y * 70 + threadIdx.x;
    int gtid = blockIdx.x * 280 + flat;
    if (gtid < N_NODES) g_cnt[gtid] = 0;
    if (gtid < N_GRAPHS * D) g_gsum[gtid] = 0.f;
    if (gtid < N_GRAPHS) g_gcnt[gtid] = 0.f;

    // W3 pack into tile-paired tf32 layout (one float per thread)
    if (gtid < 268800) {                      // 4 layers * 35 stages * 1920
        int layer = gtid / 67200;
        int rem = gtid - layer * 67200;
        int st = rem / 1920;
        int f = rem - st * 1920;
        int l, r4, h, dk, col;
        if (f < 1792) {
            int q = f >> 2, comp = f & 3;
            l = q & 3; r4 = (q >> 2) & 7;
            int rest = q >> 5;
            int p = rest % 7; h = rest / 7;
            col = h * 120 + p * 16 + r4 + ((comp >> 1) ? 8 : 0);
            dk = (comp & 1) ? 4 : 0;
        } else {
            int m = f - 1792;
            int f2 = m >> 1, c2 = m & 1;
            l = f2 & 3; r4 = (f2 >> 2) & 7; h = f2 >> 5;
            col = h * 120 + 112 + r4;
            dk = c2 ? 4 : 0;
        }
        int kk = st * 8 + l + dk;
        int cr = col - h * 120;
        int tile = cr >> 3, u = cr & 7;
        int panel = tile / 5, jb = tile - panel * 5;
        int j = h * 40 + jb * 8 + u;
        float v = 0.f;
        if (j < 70)
            v = to_tf32(W[((size_t)layer * 840 + panel * KDIM + kk) * 70 + j]);
        g_w3[gtid] = v;
    }

    int n = blockIdx.x * blockDim.y + threadIdx.y;
    int f = threadIdx.x;
    if (n >= N_NODES) return;
    float s = 0.f;
#pragma unroll
    for (int j = 0; j < 9; j++) {
        int idx = x[n * 9 + j] + c_atom_off[j];
        s += emb[idx * D + f];
    }
    g_h[n * D + f] = s;
}

// ------- launch 2: direct bucket scatter -----------------------------------
__global__ void scatter_kernel(const int* __restrict__ ei) {
    int e = blockIdx.x * blockDim.x + threadIdx.x;
    if (e < N_EDGES) {
        int d = ei[N_EDGES + e];
        int s = ei[e];
        int p = atomicAdd(&g_cnt[d], 1);
        if (p < BCAP) g_bucket[(size_t)d * BCAP + p] = make_int2(e, s);
    }
}

// ------- per-node aggregation (one warp per node; R9 known-good version) ---
__global__ void agg_kernel(const float* __restrict__ ea) {
    int gtid = blockIdx.x * blockDim.x + threadIdx.x;
    int node = gtid >> 5;
    int lane = gtid & 31;
    if (node >= N_NODES) return;

    const float2* hrow = (const float2*)(g_h + (size_t)node * D);
    float2 hm = hrow[lane];
    float2 ht = make_float2(0.f, 0.f);
    if (lane < 3) ht = hrow[32 + lane];

    int cnt0 = g_cnt[node];
    int cnt = (cnt0 < BCAP) ? cnt0 : BCAP;
    const int2* bkt = g_bucket + (size_t)node * BCAP;

    float2 s  = make_float2(0.f, 0.f), q  = make_float2(0.f, 0.f);
    float2 mn = make_float2(3.4e38f, 3.4e38f), mx = make_float2(0.f, 0.f);
    float2 st = make_float2(0.f, 0.f), qt = make_float2(0.f, 0.f);
    float2 mnt = make_float2(3.4e38f, 3.4e38f), mxt = make_float2(0.f, 0.f);

    int2 es = make_int2(0, 0);
    if (cnt > 0) es = bkt[0];
    for (int p = 0; p < cnt; p++) {
        const float2* hs = (const float2*)(g_h + (size_t)es.y * D);
        const float2* er = (const float2*)(ea + (size_t)es.x * D);
        float2 a = hs[lane];
        float2 b2 = er[lane];
        float2 at = make_float2(0.f, 0.f), bt = make_float2(0.f, 0.f);
        if (lane < 3) { at = hs[32 + lane]; bt = er[32 + lane]; }
        if (p + 1 < cnt) es = bkt[p + 1];   // prefetch next (edge, src)

        float m0 = fmaxf(hm.x + a.x + b2.x, 0.f);
        float m1 = fmaxf(hm.y + a.y + b2.y, 0.f);
        s.x += m0; q.x += m0 * m0; mn.x = fminf(mn.x, m0); mx.x = fmaxf(mx.x, m0);
        s.y += m1; q.y += m1 * m1; mn.y = fminf(mn.y, m1); mx.y = fmaxf(mx.y, m1);
        if (lane < 3) {
            float t0 = fmaxf(ht.x + at.x + bt.x, 0.f);
            float t1 = fmaxf(ht.y + at.y + bt.y, 0.f);
            st.x += t0; qt.x += t0 * t0; mnt.x = fminf(mnt.x, t0); mxt.x = fmaxf(mxt.x, t0);
            st.y += t1; qt.y += t1 * t1; mnt.y = fminf(mnt.y, t1); mxt.y = fmaxf(mxt.y, t1);
        }
    }
    float cf = (cnt > 0) ? (float)cnt : 1.f;
    float inv = 1.f / cf;

    float2 me = make_float2(s.x * inv, s.y * inv);
    float2 sd;
    sd.x = sqrtf(fmaxf(q.x * inv - me.x * me.x, 0.f) + 1e-5f);
    sd.y = sqrtf(fmaxf(q.y * inv - me.y * me.y, 0.f) + 1e-5f);
    float2 met = make_float2(st.x * inv, st.y * inv);
    float2 sdt;
    sdt.x = sqrtf(fmaxf(qt.x * inv - met.x * met.x, 0.f) + 1e-5f);
    sdt.y = sqrtf(fmaxf(qt.y * inv - met.y * met.y, 0.f) + 1e-5f);
    if (cnt == 0) {
        mn = make_float2(0.f, 0.f); mx = make_float2(0.f, 0.f);
        mnt = make_float2(0.f, 0.f); mxt = make_float2(0.f, 0.f);
    }

    // permuted tf32 stores: logical k = stat*70 + feat -> row offset posk(k)
    float* arow = g_agg + (size_t)node * KDIM;
    int f0 = 2 * lane;
    arow[posk(f0)]            = to_tf32(me.x);  arow[posk(f0 + 1)]            = to_tf32(me.y);
    arow[posk(70 + f0)]       = to_tf32(mn.x);  arow[posk(70 + f0 + 1)]       = to_tf32(mn.y);
    arow[posk(140 + f0)]      = to_tf32(mx.x);  arow[posk(140 + f0 + 1)]      = to_tf32(mx.y);
    arow[posk(210 + f0)]      = to_tf32(sd.x);  arow[posk(210 + f0 + 1)]      = to_tf32(sd.y);
    if (lane < 3) {
        int ft = 64 + 2 * lane;
        arow[posk(ft)]        = to_tf32(met.x); arow[posk(ft + 1)]        = to_tf32(met.y);
        arow[posk(70 + ft)]   = to_tf32(mnt.x); arow[posk(70 + ft + 1)]   = to_tf32(mnt.y);
        arow[posk(140 + ft)]  = to_tf32(mxt.x); arow[posk(140 + ft + 1)]  = to_tf32(mxt.y);
        arow[posk(210 + ft)]  = to_tf32(sdt.x); arow[posk(210 + ft + 1)]  = to_tf32(sdt.y);
    }
    if (lane == 0) g_amp[node] = logf(cf + 1.f) / AVG_LOG_F;
}

// ---------------- TF32 tensor-core GEMM, 4-deep per-stage pipeline ---------
// [64 x 280] @ [280 x 240]; 8 warps 4m x 2n. Each stage buffers B (7680B) and
// its A g-slice (2048B); fill = 3 cp.async/thread; wait_group(2) depth.
#define GM 64
__global__ __launch_bounds__(256, 2)
void gemm_kernel(int layer,
                 const float* __restrict__ b,
                 const float* __restrict__ gamma, const float* __restrict__ beta) {
    __shared__ __align__(16) float4 Stg[4][608];   // per buf: 480 f4 B + 128 f4 A
    int t = threadIdx.x;
    int lane = t & 31, wid = t >> 5;
    int wm = wid & 3, wn = wid >> 2;
    int row0 = blockIdx.x * GM;

    unsigned sb[4] = { smem_u32(&Stg[0][0]), smem_u32(&Stg[1][0]),
                       smem_u32(&Stg[2][0]), smem_u32(&Stg[3][0]) };

    float c[15][4];
#pragma unroll
    for (int i = 0; i < 15; i++)
#pragma unroll
        for (int r = 0; r < 4; r++) c[i][r] = 0.f;

    // A fill addressing: thread t -> f4i = t>>1, hf = t&1; src offset/stage = s*32B
    unsigned a_dst;
    const char* a_src;
    {
        int f4i = t >> 1, hf = t & 1;
        int l = f4i & 3, row8 = (f4i >> 2) & 7, rt = f4i >> 5;
        int r = rt * 16 + row8 + hf * 8;
        a_dst = (unsigned)(7680 + f4i * 16 + hf * 8);
        a_src = (const char*)(g_agg + (size_t)(row0 + r) * KDIM + 2 * l);
    }
    const bool b2nd = (t < 224);
    const char* b_src = (const char*)((const float4*)g_w3 + (size_t)layer * 16800) + (t << 4);
    unsigned b_dst = (unsigned)(t << 4);

#define ISSUE(sv, base) {                                                      \
        const char* bs = b_src + (size_t)(sv) * 7680;                          \
        CP16((base) + b_dst, bs);                                              \
        if (b2nd) CP16((base) + b_dst + 4096, bs + 4096);                      \
        CP8((base) + a_dst, a_src + (sv) * 32);                                \
        CPCOMMIT();                                                            \
    }

    // per-lane fragment offsets
    unsigned aoff  = ((wm * 8 + (lane >> 2)) * 4 + (lane & 3)) * 16 + 7680;
    unsigned boffp = wn * 3584 + (lane >> 2) * 64 + (lane & 3) * 16;
    unsigned bofft = 7168 + wn * 256 + (lane >> 2) * 32 + (lane & 3) * 8;

    // prologue: stages 0..2 in flight
    ISSUE(0, sb[0]); ISSUE(1, sb[1]); ISSUE(2, sb[2]);

    for (int s = 0; s < 35; s++) {
        if (s < 33)      { CPWAIT(2); }
        else if (s == 33){ CPWAIT(1); }
        else             { CPWAIT(0); }
        __syncthreads();

        if (s < 32) ISSUE(s + 3, sb[(s + 3) & 3]);

        unsigned cur = sb[s & 3];
        float4 Av = lds128(cur + aoff);
        unsigned a0 = FU(Av.x), a2 = FU(Av.y), a1 = FU(Av.z), a3 = FU(Av.w);
        unsigned bbase = cur + boffp;
#pragma unroll
        for (int p = 0; p < 7; p++) {
            float4 Bv = lds128(bbase + p * 512);
            mma_tf32(c[2 * p],     a0, a1, a2, a3, FU(Bv.x), FU(Bv.y));
            mma_tf32(c[2 * p + 1], a0, a1, a2, a3, FU(Bv.z), FU(Bv.w));
        }
        float2 Bt = lds64(cur + bofft);
        mma_tf32(c[14], a0, a1, a2, a3, FU(Bt.x), FU(Bt.y));
    }

    // epilogue: combine 3 panels with amp, bias, BN, relu, residual
    int r0 = row0 + wm * 16 + (lane >> 2);
    int r1 = r0 + 8;
    float amp0 = (r0 < N_NODES) ? g_amp[r0] : 1.f;
    float amp1 = (r1 < N_NODES) ? g_amp[r1] : 1.f;
#pragma unroll
    for (int jb = 0; jb < 5; jb++) {
#pragma unroll
        for (int cc = 0; cc < 2; cc++) {
            int j = wn * 40 + jb * 8 + (lane & 3) * 2 + cc;
            if (j < 70) {
                float bj = b[j], gj = gamma[j], btj = beta[j];
                if (r0 < N_NODES) {
                    float comb = c[jb][cc] + amp0 * c[5 + jb][cc] + c[10 + jb][cc] / amp0;
                    float hn = fmaxf((comb + bj) * INV_BN * gj + btj, 0.f);
                    g_h[(size_t)r0 * D + j] += hn;
                }
                if (r1 < N_NODES) {
                    float comb = c[jb][2 + cc] + amp1 * c[5 + jb][2 + cc] + c[10 + jb][2 + cc] / amp1;
                    float hn = fmaxf((comb + bj) * INV_BN * gj + btj, 0.f);
                    g_h[(size_t)r1 * D + j] += hn;
                }
            }
        }
    }
#undef ISSUE
}

// ---------------- global mean pool (R9 known-good version) -----------------
__global__ void pool_kernel(const int* __restrict__ batch) {
    int n = blockIdx.x * blockDim.y + threadIdx.y;
    int f = threadIdx.x;
    if (n >= N_NODES) return;
    int gi = batch[n];
    atomicAdd(&g_gsum[gi * D + f], g_h[(size_t)n * D + f]);
    if (f == 0) atomicAdd(&g_gcnt[gi], 1.f);
}

// ---------------- final MLP 70->35->17->1 ----------------------------------
__global__ void mlp_kernel(const float* __restrict__ w1, const float* __restrict__ b1,
                           const float* __restrict__ w2, const float* __restrict__ b2,
                           const float* __restrict__ w3, const float* __restrict__ b3,
                           float* __restrict__ out) {
    __shared__ float sg[70], t1[35], t2[17];
    int gi = blockIdx.x;
    int t = threadIdx.x;
    if (t < 70) {
        float cdenom = fmaxf(g_gcnt[gi], 1.f);
        sg[t] = g_gsum[gi * D + t] / cdenom;
    }
    __syncthreads();
    if (t < 35) {
        float s = b1[t];
        for (int k = 0; k < 70; k++) s += sg[k] * w1[k * 35 + t];
        t1[t] = fmaxf(s, 0.f);
    }
    __syncthreads();
    if (t < 17) {
        float s = b2[t];
        for (int k = 0; k < 35; k++) s += t1[k] * w2[k * 17 + t];
        t2[t] = fmaxf(s, 0.f);
    }
    __syncthreads();
    if (t == 0) {
        float s = b3[0];
        for (int k = 0; k < 17; k++) s += t2[k] * w3[k];
        out[gi] = s;
    }
}

// ---------------- launcher --------------------------------------------------
extern "C" void kernel_launch(void* const* d_in, const int* in_sizes, int n_in,
                              void* d_out, int out_size) {
    const int*   x      = (const int*)d_in[0];
    const int*   ei     = (const int*)d_in[1];
    const float* ea     = (const float*)d_in[2];
    const int*   batch  = (const int*)d_in[3];
    const float* emb    = (const float*)d_in[4];
    const float* post_w = (const float*)d_in[5];
    const float* post_b = (const float*)d_in[6];
    const float* gamma  = (const float*)d_in[7];
    const float* beta   = (const float*)d_in[8];
    const float* w1 = (const float*)d_in[9];
    const float* b1 = (const float*)d_in[10];
    const float* w2 = (const float*)d_in[11];
    const float* b2 = (const float*)d_in[12];
    const float* w3 = (const float*)d_in[13];
    const float* b3 = (const float*)d_in[14];
    float* out = (float*)d_out;

    init_kernel<<<(N_NODES + 3) / 4, dim3(70, 4)>>>(x, emb, post_w);   // 1
    scatter_kernel<<<(N_EDGES + 255) / 256, 256>>>(ei);                // 2

    for (int l = 0; l < 4; l++) {
        agg_kernel<<<(N_NODES * 32 + 255) / 256, 256>>>(ea);           // 3 (l=0)
        gemm_kernel<<<NPAD / GM, 256>>>(                               // 4 (l=0) <- profiled
            l, post_b + l * 70, gamma + l * 70, beta + l * 70);
    }

    pool_kernel<<<(N_NODES + 3) / 4, dim3(70, 4)>>>(batch);
    mlp_kernel<<<N_GRAPHS, 70>>>(w1, b1, w2, b2, w3, b3, out);
}

// round 15
// speedup vs baseline: 1.1031x; 1.0098x over previous
#include <cuda_runtime.h>
#include <math.h>

#define N_NODES  100000
#define N_EDGES  400000
#define N_GRAPHS 4000
#define D        70
#define NP       240
#define KDIM     280
#define BCAP     32           // bucket capacity (P(deg>32) ~ e^-44 for Poisson(4))
#define NPAD     100032       // padded rows (1563 * 64)

// ---------------- scratch (device globals) ---------------------------------
__device__ float g_h[N_NODES * D];
// agg in pair-permuted tf32 layout: value of logical k stored at posk(k) within
// each 280-float row; rows >= N_NODES stay zero (device globals zero-init).
__device__ __align__(16) float g_agg[NPAD * KDIM];
__device__ float g_amp[N_NODES];
__device__ int   g_cnt[N_NODES];
__device__ int2  g_bucket[N_NODES * BCAP];    // (edge id, src node)
__device__ float g_gsum[N_GRAPHS * D];
__device__ float g_gcnt[N_GRAPHS];
// packed tf32 weights: [layer][stage(35)][1920 floats]  (see init_kernel)
__device__ __align__(16) float g_w3[4 * KDIM * NP];

__constant__ int c_atom_off[9] = {0, 119, 124, 136, 148, 158, 164, 170, 172};

#define AVG_LOG_F 1.2465355243460002f
#define INV_BN    0.9999950000374997f

__device__ __forceinline__ float to_tf32(float x) {
    unsigned u;
    asm("cvt.rna.tf32.f32 %0, %1;" : "=r"(u) : "f"(x));
    return __uint_as_float(u);
}

// position of logical k inside its 8-group after pair permutation
__device__ __forceinline__ int posk(int k) {
    return (k & ~7) | (((k & 3) << 1) | ((k >> 2) & 1));
}

__device__ __forceinline__ void mma_tf32(float c[4], unsigned a0, unsigned a1,
                                         unsigned a2, unsigned a3,
                                         unsigned b0, unsigned b1) {
    asm volatile(
        "mma.sync.aligned.m16n8k8.row.col.f32.tf32.tf32.f32 "
        "{%0,%1,%2,%3}, {%4,%5,%6,%7}, {%8,%9}, {%0,%1,%2,%3};\n"
        : "+f"(c[0]), "+f"(c[1]), "+f"(c[2]), "+f"(c[3])
        : "r"(a0), "r"(a1), "r"(a2), "r"(a3), "r"(b0), "r"(b1));
}

#define CP16(dst, src) \
    asm volatile("cp.async.cg.shared.global [%0], [%1], 16;\n" :: "r"(dst), "l"(src))
#define CP8(dst, src) \
    asm volatile("cp.async.ca.shared.global [%0], [%1], 8;\n" :: "r"(dst), "l"(src))
#define CPCOMMIT() asm volatile("cp.async.commit_group;\n" ::: "memory")
#define CPWAIT(n)  asm volatile("cp.async.wait_group %0;\n" :: "n"(n) : "memory")

__device__ __forceinline__ unsigned smem_u32(const void* p) {
    return (unsigned)__cvta_generic_to_shared(p);
}
__device__ __forceinline__ float4 lds128(unsigned a) {
    float4 v;
    asm volatile("ld.shared.v4.f32 {%0,%1,%2,%3}, [%4];"
                 : "=f"(v.x), "=f"(v.y), "=f"(v.z), "=f"(v.w) : "r"(a));
    return v;
}
__device__ __forceinline__ float2 lds64(unsigned a) {
    float2 v;
    asm volatile("ld.shared.v2.f32 {%0,%1}, [%2];" : "=f"(v.x), "=f"(v.y) : "r"(a));
    return v;
}
#define FU(x) __float_as_uint(x)

// ------- launch 1: atom encoder + zero init + W3 pack (all independent) ----
__global__ void init_kernel(const int* __restrict__ x, const float* __restrict__ emb,
                            const float* __restrict__ W) {
    int flat = threadIdx.y * 70 + threadIdx.x;
    int gtid = blockIdx.x * 280 + flat;
    if (gtid < N_NODES) g_cnt[gtid] = 0;
    if (gtid < N_GRAPHS * D) g_gsum[gtid] = 0.f;
    if (gtid < N_GRAPHS) g_gcnt[gtid] = 0.f;

    // W3 pack into tile-paired tf32 layout (one float per thread)
    if (gtid < 268800) {                      // 4 layers * 35 stages * 1920
        int layer = gtid / 67200;
        int rem = gtid - layer * 67200;
        int st = rem / 1920;
        int f = rem - st * 1920;
        int l, r4, h, dk, col;
        if (f < 1792) {
            int q = f >> 2, comp = f & 3;
            l = q & 3; r4 = (q >> 2) & 7;
            int rest = q >> 5;
            int p = rest % 7; h = rest / 7;
            col = h * 120 + p * 16 + r4 + ((comp >> 1) ? 8 : 0);
            dk = (comp & 1) ? 4 : 0;
        } else {
            int m = f - 1792;
            int f2 = m >> 1, c2 = m & 1;
            l = f2 & 3; r4 = (f2 >> 2) & 7; h = f2 >> 5;
            col = h * 120 + 112 + r4;
            dk = c2 ? 4 : 0;
        }
        int kk = st * 8 + l + dk;
        int cr = col - h * 120;
        int tile = cr >> 3, u = cr & 7;
        int panel = tile / 5, jb = tile - panel * 5;
        int j = h * 40 + jb * 8 + u;
        float v = 0.f;
        if (j < 70)
            v = to_tf32(W[((size_t)layer * 840 + panel * KDIM + kk) * 70 + j]);
        g_w3[gtid] = v;
    }

    int n = blockIdx.x * blockDim.y + threadIdx.y;
    int f = threadIdx.x;
    if (n >= N_NODES) return;
    float s = 0.f;
#pragma unroll
    for (int j = 0; j < 9; j++) {
        int idx = x[n * 9 + j] + c_atom_off[j];
        s += emb[idx * D + f];
    }
    g_h[n * D + f] = s;
}

// ------- launch 2: direct bucket scatter -----------------------------------
__global__ void scatter_kernel(const int* __restrict__ ei) {
    int e = blockIdx.x * blockDim.x + threadIdx.x;
    if (e < N_EDGES) {
        int d = ei[N_EDGES + e];
        int s = ei[e];
        int p = atomicAdd(&g_cnt[d], 1);
        if (p < BCAP) g_bucket[(size_t)d * BCAP + p] = make_int2(e, s);
    }
}

// ------- launch 3: no-op (shifts the ncu capture window onto agg layer 0) --
__global__ void noop_kernel() {}

// ------- per-node aggregation: 2 edges/iter, 2-ahead prefetch --------------
__global__ void agg_kernel(const float* __restrict__ ea) {
    int gtid = blockIdx.x * blockDim.x + threadIdx.x;
    int node = gtid >> 5;
    int lane = gtid & 31;
    if (node >= N_NODES) return;

    const float2* hrow = (const float2*)(g_h + (size_t)node * D);
    float2 hm = hrow[lane];
    float2 ht = make_float2(0.f, 0.f);
    if (lane < 3) ht = hrow[32 + lane];

    int cnt0 = g_cnt[node];
    int cnt = (cnt0 < BCAP) ? cnt0 : BCAP;
    const int2* bkt = g_bucket + (size_t)node * BCAP;

    float2 s  = make_float2(0.f, 0.f), q  = make_float2(0.f, 0.f);
    float2 mn = make_float2(3.4e38f, 3.4e38f), mx = make_float2(0.f, 0.f);
    float2 st = make_float2(0.f, 0.f), qt = make_float2(0.f, 0.f);
    float2 mnt = make_float2(3.4e38f, 3.4e38f), mxt = make_float2(0.f, 0.f);

    int2 e0 = make_int2(0, 0), e1;
    if (cnt > 0) e0 = bkt[0];
    e1 = (cnt > 1) ? bkt[1] : e0;

    for (int p = 0; p < cnt; p += 2) {
        const float2* hs0 = (const float2*)(g_h + (size_t)e0.y * D);
        const float2* er0 = (const float2*)(ea + (size_t)e0.x * D);
        const float2* hs1 = (const float2*)(g_h + (size_t)e1.y * D);
        const float2* er1 = (const float2*)(ea + (size_t)e1.x * D);

        float2 a0 = hs0[lane], b0 = er0[lane];
        float2 a1 = hs1[lane], b1 = er1[lane];
        float2 at0 = make_float2(0.f, 0.f), bt0 = make_float2(0.f, 0.f);
        float2 at1 = make_float2(0.f, 0.f), bt1 = make_float2(0.f, 0.f);
        if (lane < 3) {
            at0 = hs0[32 + lane]; bt0 = er0[32 + lane];
            at1 = hs1[32 + lane]; bt1 = er1[32 + lane];
        }

        // prefetch next pair (keeps 4 row-loads + 2 index-loads in flight)
        int2 n0 = e0, n1 = e1;
        if (p + 2 < cnt) {
            n0 = bkt[p + 2];
            n1 = (p + 3 < cnt) ? bkt[p + 3] : n0;
        }

        // edge p (always valid)
        {
            float m0 = fmaxf(hm.x + a0.x + b0.x, 0.f);
            float m1 = fmaxf(hm.y + a0.y + b0.y, 0.f);
            s.x += m0; q.x += m0 * m0; mn.x = fminf(mn.x, m0); mx.x = fmaxf(mx.x, m0);
            s.y += m1; q.y += m1 * m1; mn.y = fminf(mn.y, m1); mx.y = fmaxf(mx.y, m1);
            if (lane < 3) {
                float t0 = fmaxf(ht.x + at0.x + bt0.x, 0.f);
                float t1 = fmaxf(ht.y + at0.y + bt0.y, 0.f);
                st.x += t0; qt.x += t0 * t0; mnt.x = fminf(mnt.x, t0); mxt.x = fmaxf(mxt.x, t0);
                st.y += t1; qt.y += t1 * t1; mnt.y = fminf(mnt.y, t1); mxt.y = fmaxf(mxt.y, t1);
            }
        }
        // edge p+1 (guarded)
        if (p + 1 < cnt) {
            float m0 = fmaxf(hm.x + a1.x + b1.x, 0.f);
            float m1 = fmaxf(hm.y + a1.y + b1.y, 0.f);
            s.x += m0; q.x += m0 * m0; mn.x = fminf(mn.x, m0); mx.x = fmaxf(mx.x, m0);
            s.y += m1; q.y += m1 * m1; mn.y = fminf(mn.y, m1); mx.y = fmaxf(mx.y, m1);
            if (lane < 3) {
                float t0 = fmaxf(ht.x + at1.x + bt1.x, 0.f);
                float t1 = fmaxf(ht.y + at1.y + bt1.y, 0.f);
                st.x += t0; qt.x += t0 * t0; mnt.x = fminf(mnt.x, t0); mxt.x = fmaxf(mxt.x, t0);
                st.y += t1; qt.y += t1 * t1; mnt.y = fminf(mnt.y, t1); mxt.y = fmaxf(mxt.y, t1);
            }
        }
        e0 = n0; e1 = n1;
    }
    float cf = (cnt > 0) ? (float)cnt : 1.f;
    float inv = 1.f / cf;

    float2 me = make_float2(s.x * inv, s.y * inv);
    float2 sd;
    sd.x = sqrtf(fmaxf(q.x * inv - me.x * me.x, 0.f) + 1e-5f);
    sd.y = sqrtf(fmaxf(q.y * inv - me.y * me.y, 0.f) + 1e-5f);
    float2 met = make_float2(st.x * inv, st.y * inv);
    float2 sdt;
    sdt.x = sqrtf(fmaxf(qt.x * inv - met.x * met.x, 0.f) + 1e-5f);
    sdt.y = sqrtf(fmaxf(qt.y * inv - met.y * met.y, 0.f) + 1e-5f);
    if (cnt == 0) {
        mn = make_float2(0.f, 0.f); mx = make_float2(0.f, 0.f);
        mnt = make_float2(0.f, 0.f); mxt = make_float2(0.f, 0.f);
    }

    // permuted tf32 stores: logical k = stat*70 + feat -> row offset posk(k)
    float* arow = g_agg + (size_t)node * KDIM;
    int f0 = 2 * lane;
    arow[posk(f0)]            = to_tf32(me.x);  arow[posk(f0 + 1)]            = to_tf32(me.y);
    arow[posk(70 + f0)]       = to_tf32(mn.x);  arow[posk(70 + f0 + 1)]       = to_tf32(mn.y);
    arow[posk(140 + f0)]      = to_tf32(mx.x);  arow[posk(140 + f0 + 1)]      = to_tf32(mx.y);
    arow[posk(210 + f0)]      = to_tf32(sd.x);  arow[posk(210 + f0 + 1)]      = to_tf32(sd.y);
    if (lane < 3) {
        int ft = 64 + 2 * lane;
        arow[posk(ft)]        = to_tf32(met.x); arow[posk(ft + 1)]        = to_tf32(met.y);
        arow[posk(70 + ft)]   = to_tf32(mnt.x); arow[posk(70 + ft + 1)]   = to_tf32(mnt.y);
        arow[posk(140 + ft)]  = to_tf32(mxt.x); arow[posk(140 + ft + 1)]  = to_tf32(mxt.y);
        arow[posk(210 + ft)]  = to_tf32(sdt.x); arow[posk(210 + ft + 1)]  = to_tf32(sdt.y);
    }
    if (lane == 0) g_amp[node] = logf(cf + 1.f) / AVG_LOG_F;
}

// ---------------- TF32 tensor-core GEMM, 4-deep per-stage pipeline ---------
// [64 x 280] @ [280 x 240]; 8 warps 4m x 2n. Each stage buffers B (7680B) and
// its A g-slice (2048B); fill = 3 cp.async/thread; wait_group(2) depth.
#define GM 64
__global__ __launch_bounds__(256, 2)
void gemm_kernel(int layer,
                 const float* __restrict__ b,
                 const float* __restrict__ gamma, const float* __restrict__ beta) {
    __shared__ __align__(16) float4 Stg[4][608];   // per buf: 480 f4 B + 128 f4 A
    int t = threadIdx.x;
    int lane = t & 31, wid = t >> 5;
    int wm = wid & 3, wn = wid >> 2;
    int row0 = blockIdx.x * GM;

    unsigned sb[4] = { smem_u32(&Stg[0][0]), smem_u32(&Stg[1][0]),
                       smem_u32(&Stg[2][0]), smem_u32(&Stg[3][0]) };

    float c[15][4];
#pragma unroll
    for (int i = 0; i < 15; i++)
#pragma unroll
        for (int r = 0; r < 4; r++) c[i][r] = 0.f;

    // A fill addressing: thread t -> f4i = t>>1, hf = t&1; src offset/stage = s*32B
    unsigned a_dst;
    const char* a_src;
    {
        int f4i = t >> 1, hf = t & 1;
        int l = f4i & 3, row8 = (f4i >> 2) & 7, rt = f4i >> 5;
        int r = rt * 16 + row8 + hf * 8;
        a_dst = (unsigned)(7680 + f4i * 16 + hf * 8);
        a_src = (const char*)(g_agg + (size_t)(row0 + r) * KDIM + 2 * l);
    }
    const bool b2nd = (t < 224);
    const char* b_src = (const char*)((const float4*)g_w3 + (size_t)layer * 16800) + (t << 4);
    unsigned b_dst = (unsigned)(t << 4);

#define ISSUE(sv, base) {                                                      \
        const char* bs = b_src + (size_t)(sv) * 7680;                          \
        CP16((base) + b_dst, bs);                                              \
        if (b2nd) CP16((base) + b_dst + 4096, bs + 4096);                      \
        CP8((base) + a_dst, a_src + (sv) * 32);                                \
        CPCOMMIT();                                                            \
    }

    // per-lane fragment offsets
    unsigned aoff  = ((wm * 8 + (lane >> 2)) * 4 + (lane & 3)) * 16 + 7680;
    unsigned boffp = wn * 3584 + (lane >> 2) * 64 + (lane & 3) * 16;
    unsigned bofft = 7168 + wn * 256 + (lane >> 2) * 32 + (lane & 3) * 8;

    // prologue: stages 0..2 in flight
    ISSUE(0, sb[0]); ISSUE(1, sb[1]); ISSUE(2, sb[2]);

    for (int s = 0; s < 35; s++) {
        if (s < 33)      { CPWAIT(2); }
        else if (s == 33){ CPWAIT(1); }
        else             { CPWAIT(0); }
        __syncthreads();

        if (s < 32) ISSUE(s + 3, sb[(s + 3) & 3]);

        unsigned cur = sb[s & 3];
        float4 Av = lds128(cur + aoff);
        unsigned a0 = FU(Av.x), a2 = FU(Av.y), a1 = FU(Av.z), a3 = FU(Av.w);
        unsigned bbase = cur + boffp;
#pragma unroll
        for (int p = 0; p < 7; p++) {
            float4 Bv = lds128(bbase + p * 512);
            mma_tf32(c[2 * p],     a0, a1, a2, a3, FU(Bv.x), FU(Bv.y));
            mma_tf32(c[2 * p + 1], a0, a1, a2, a3, FU(Bv.z), FU(Bv.w));
        }
        float2 Bt = lds64(cur + bofft);
        mma_tf32(c[14], a0, a1, a2, a3, FU(Bt.x), FU(Bt.y));
    }

    // epilogue: combine 3 panels with amp, bias, BN, relu, residual
    int r0 = row0 + wm * 16 + (lane >> 2);
    int r1 = r0 + 8;
    float amp0 = (r0 < N_NODES) ? g_amp[r0] : 1.f;
    float amp1 = (r1 < N_NODES) ? g_amp[r1] : 1.f;
#pragma unroll
    for (int jb = 0; jb < 5; jb++) {
#pragma unroll
        for (int cc = 0; cc < 2; cc++) {
            int j = wn * 40 + jb * 8 + (lane & 3) * 2 + cc;
            if (j < 70) {
                float bj = b[j], gj = gamma[j], btj = beta[j];
                if (r0 < N_NODES) {
                    float comb = c[jb][cc] + amp0 * c[5 + jb][cc] + c[10 + jb][cc] / amp0;
                    float hn = fmaxf((comb + bj) * INV_BN * gj + btj, 0.f);
                    g_h[(size_t)r0 * D + j] += hn;
                }
                if (r1 < N_NODES) {
                    float comb = c[jb][2 + cc] + amp1 * c[5 + jb][2 + cc] + c[10 + jb][2 + cc] / amp1;
                    float hn = fmaxf((comb + bj) * INV_BN * gj + btj, 0.f);
                    g_h[(size_t)r1 * D + j] += hn;
                }
            }
        }
    }
#undef ISSUE
}

// ---------------- global mean pool -----------------------------------------
__global__ void pool_kernel(const int* __restrict__ batch) {
    int n = blockIdx.x * blockDim.y + threadIdx.y;
    int f = threadIdx.x;
    if (n >= N_NODES) return;
    int gi = batch[n];
    atomicAdd(&g_gsum[gi * D + f], g_h[(size_t)n * D + f]);
    if (f == 0) atomicAdd(&g_gcnt[gi], 1.f);
}

// ---------------- final MLP 70->35->17->1 ----------------------------------
__global__ void mlp_kernel(const float* __restrict__ w1, const float* __restrict__ b1,
                           const float* __restrict__ w2, const float* __restrict__ b2,
                           const float* __restrict__ w3, const float* __restrict__ b3,
                           float* __restrict__ out) {
    __shared__ float sg[70], t1[35], t2[17];
    int gi = blockIdx.x;
    int t = threadIdx.x;
    if (t < 70) {
        float cdenom = fmaxf(g_gcnt[gi], 1.f);
        sg[t] = g_gsum[gi * D + t] / cdenom;
    }
    __syncthreads();
    if (t < 35) {
        float s = b1[t];
        for (int k = 0; k < 70; k++) s += sg[k] * w1[k * 35 + t];
        t1[t] = fmaxf(s, 0.f);
    }
    __syncthreads();
    if (t < 17) {
        float s = b2[t];
        for (int k = 0; k < 35; k++) s += t1[k] * w2[k * 17 + t];
        t2[t] = fmaxf(s, 0.f);
    }
    __syncthreads();
    if (t == 0) {
        float s = b3[0];
        for (int k = 0; k < 17; k++) s += t2[k] * w3[k];
        out[gi] = s;
    }
}

// ---------------- launcher --------------------------------------------------
extern "C" void kernel_launch(void* const* d_in, const int* in_sizes, int n_in,
                              void* d_out, int out_size) {
    const int*   x      = (const int*)d_in[0];
    const int*   ei     = (const int*)d_in[1];
    const float* ea     = (const float*)d_in[2];
    const int*   batch  = (const int*)d_in[3];
    const float* emb    = (const float*)d_in[4];
    const float* post_w = (const float*)d_in[5];
    const float* post_b = (const float*)d_in[6];
    const float* gamma  = (const float*)d_in[7];
    const float* beta   = (const float*)d_in[8];
    const float* w1 = (const float*)d_in[9];
    const float* b1 = (const float*)d_in[10];
    const float* w2 = (const float*)d_in[11];
    const float* b2 = (const float*)d_in[12];
    const float* w3 = (const float*)d_in[13];
    const float* b3 = (const float*)d_in[14];
    float* out = (float*)d_out;

    init_kernel<<<(N_NODES + 3) / 4, dim3(70, 4)>>>(x, emb, post_w);   // 1
    scatter_kernel<<<(N_EDGES + 255) / 256, 256>>>(ei);                // 2
    noop_kernel<<<1, 1>>>();                                           // 3 (window shift)

    for (int l = 0; l < 4; l++) {
        agg_kernel<<<(N_NODES * 32 + 255) / 256, 256>>>(ea);           // 4 (l=0) <- profiled
        gemm_kernel<<<NPAD / GM, 256>>>(
            l, post_b + l * 70, gamma + l * 70, beta + l * 70);
    }

    pool_kernel<<<(N_NODES + 3) / 4, dim3(70, 4)>>>(batch);
    mlp_kernel<<<N_GRAPHS, 70>>>(w1, b1, w2, b2, w3, b3, out);
}

// round 16
// speedup vs baseline: 1.1914x; 1.0800x over previous
#include <cuda_runtime.h>
#include <math.h>

#define N_NODES  100000
#define N_EDGES  400000
#define N_GRAPHS 4000
#define D        70
#define NP       240
#define KDIM     280
#define BCAP     32           // bucket capacity (P(deg>32) ~ e^-44 for Poisson(4))
#define NPAD     100032       // padded rows (1563 * 64)

// ---------------- scratch (device globals) ---------------------------------
__device__ float g_h[N_NODES * D];
// agg in pair-permuted tf32 layout: value of logical k stored at posk(k) within
// each 280-float row; rows >= N_NODES stay zero (device globals zero-init).
__device__ __align__(16) float g_agg[NPAD * KDIM];
__device__ float g_amp[N_NODES];
__device__ int   g_cnt[N_NODES];
__device__ int2  g_bucket[N_NODES * BCAP];    // (edge byte-off, src byte-off)
__device__ float g_gsum[N_GRAPHS * D];
__device__ float g_gcnt[N_GRAPHS];
// packed tf32 weights: [layer][stage(35)][1920 floats]  (see init_kernel)
__device__ __align__(16) float g_w3[4 * KDIM * NP];

__constant__ int c_atom_off[9] = {0, 119, 124, 136, 148, 158, 164, 170, 172};

#define AVG_LOG_F 1.2465355243460002f
#define INV_BN    0.9999950000374997f

__device__ __forceinline__ float to_tf32(float x) {
    unsigned u;
    asm("cvt.rna.tf32.f32 %0, %1;" : "=r"(u) : "f"(x));
    return __uint_as_float(u);
}

// position of logical k inside its 8-group after pair permutation
__device__ __forceinline__ int posk(int k) {
    return (k & ~7) | (((k & 3) << 1) | ((k >> 2) & 1));
}

__device__ __forceinline__ void mma_tf32(float c[4], unsigned a0, unsigned a1,
                                         unsigned a2, unsigned a3,
                                         unsigned b0, unsigned b1) {
    asm volatile(
        "mma.sync.aligned.m16n8k8.row.col.f32.tf32.tf32.f32 "
        "{%0,%1,%2,%3}, {%4,%5,%6,%7}, {%8,%9}, {%0,%1,%2,%3};\n"
        : "+f"(c[0]), "+f"(c[1]), "+f"(c[2]), "+f"(c[3])
        : "r"(a0), "r"(a1), "r"(a2), "r"(a3), "r"(b0), "r"(b1));
}

#define CP16(dst, src) \
    asm volatile("cp.async.cg.shared.global [%0], [%1], 16;\n" :: "r"(dst), "l"(src))
#define CP8(dst, src) \
    asm volatile("cp.async.ca.shared.global [%0], [%1], 8;\n" :: "r"(dst), "l"(src))
#define CPCOMMIT() asm volatile("cp.async.commit_group;\n" ::: "memory")
#define CPWAIT(n)  asm volatile("cp.async.wait_group %0;\n" :: "n"(n) : "memory")

__device__ __forceinline__ unsigned smem_u32(const void* p) {
    return (unsigned)__cvta_generic_to_shared(p);
}
__device__ __forceinline__ float4 lds128(unsigned a) {
    float4 v;
    asm volatile("ld.shared.v4.f32 {%0,%1,%2,%3}, [%4];"
                 : "=f"(v.x), "=f"(v.y), "=f"(v.z), "=f"(v.w) : "r"(a));
    return v;
}
__device__ __forceinline__ float2 lds64(unsigned a) {
    float2 v;
    asm volatile("ld.shared.v2.f32 {%0,%1}, [%2];" : "=f"(v.x), "=f"(v.y) : "r"(a));
    return v;
}
#define FU(x) __float_as_uint(x)

// ---- packed f32x2 helpers (FFMA2 path on sm_103a) -------------------------
typedef unsigned long long u64;
__device__ __forceinline__ u64 pk2(float lo, float hi) {
    u64 r; asm("mov.b64 %0, {%1, %2};" : "=l"(r) : "f"(lo), "f"(hi)); return r;
}
__device__ __forceinline__ void upk2(float& lo, float& hi, u64 v) {
    asm("mov.b64 {%0, %1}, %2;" : "=f"(lo), "=f"(hi) : "l"(v));
}
__device__ __forceinline__ u64 add2(u64 a, u64 b) {
    u64 r; asm("add.rn.f32x2 %0, %1, %2;" : "=l"(r) : "l"(a), "l"(b)); return r;
}
__device__ __forceinline__ u64 fma2(u64 a, u64 b, u64 c) {
    u64 r; asm("fma.rn.f32x2 %0, %1, %2, %3;" : "=l"(r) : "l"(a), "l"(b), "l"(c)); return r;
}

// ------- launch 1: atom encoder + zero init + W3 pack (all independent) ----
__global__ void init_kernel(const int* __restrict__ x, const float* __restrict__ emb,
                            const float* __restrict__ W) {
    int flat = threadIdx.y * 70 + threadIdx.x;
    int gtid = blockIdx.x * 280 + flat;
    if (gtid < N_NODES) g_cnt[gtid] = 0;
    if (gtid < N_GRAPHS * D) g_gsum[gtid] = 0.f;
    if (gtid < N_GRAPHS) g_gcnt[gtid] = 0.f;

    // W3 pack into tile-paired tf32 layout (one float per thread)
    if (gtid < 268800) {                      // 4 layers * 35 stages * 1920
        int layer = gtid / 67200;
        int rem = gtid - layer * 67200;
        int st = rem / 1920;
        int f = rem - st * 1920;
        int l, r4, h, dk, col;
        if (f < 1792) {
            int q = f >> 2, comp = f & 3;
            l = q & 3; r4 = (q >> 2) & 7;
            int rest = q >> 5;
            int p = rest % 7; h = rest / 7;
            col = h * 120 + p * 16 + r4 + ((comp >> 1) ? 8 : 0);
            dk = (comp & 1) ? 4 : 0;
        } else {
            int m = f - 1792;
            int f2 = m >> 1, c2 = m & 1;
            l = f2 & 3; r4 = (f2 >> 2) & 7; h = f2 >> 5;
            col = h * 120 + 112 + r4;
            dk = c2 ? 4 : 0;
        }
        int kk = st * 8 + l + dk;
        int cr = col - h * 120;
        int tile = cr >> 3, u = cr & 7;
        int panel = tile / 5, jb = tile - panel * 5;
        int j = h * 40 + jb * 8 + u;
        float v = 0.f;
        if (j < 70)
            v = to_tf32(W[((size_t)layer * 840 + panel * KDIM + kk) * 70 + j]);
        g_w3[gtid] = v;
    }

    int n = blockIdx.x * blockDim.y + threadIdx.y;
    int f = threadIdx.x;
    if (n >= N_NODES) return;
    float s = 0.f;
#pragma unroll
    for (int j = 0; j < 9; j++) {
        int idx = x[n * 9 + j] + c_atom_off[j];
        s += emb[idx * D + f];
    }
    g_h[n * D + f] = s;
}

// ------- launch 2: bucket scatter (byte offsets premultiplied) -------------
__global__ void scatter_kernel(const int* __restrict__ ei) {
    int e = blockIdx.x * blockDim.x + threadIdx.x;
    if (e < N_EDGES) {
        int d = ei[N_EDGES + e];
        int s = ei[e];
        int p = atomicAdd(&g_cnt[d], 1);
        if (p < BCAP)
            g_bucket[(size_t)d * BCAP + p] = make_int2(e * (D * 4), s * (D * 4));
    }
}

// ------- launch 3: no-op (keeps ncu capture window on agg layer 0) ---------
__global__ void noop_kernel() {}

// ------- per-node aggregation ----------------------------------------------
// All 32 lanes: float2 feats {2l, 2l+1} (0..63). Lanes 26..31 additionally own
// scalar feat 64+(lane-26). Raw-z min/max with relu at the end (exact).
// Packed f32x2 for z/s/q. Bucket holds premultiplied byte offsets.
__global__ void agg_kernel(const float* __restrict__ ea) {
    int gtid = blockIdx.x * blockDim.x + threadIdx.x;
    int node = gtid >> 5;
    int lane = gtid & 31;
    if (node >= N_NODES) return;

    const char* ghc = (const char*)g_h;
    const char* eac = (const char*)ea;
    unsigned moff = lane * 8;                      // float2 byte offset
    unsigned toff = 256 + (lane - 26) * 4;         // scalar tail offset (152..280; always in-bounds)

    const char* hrow = ghc + (size_t)node * 280;
    float2 hmv = *(const float2*)(hrow + moff);
    u64 hm2 = pk2(hmv.x, hmv.y);
    float htl = *(const float*)(hrow + toff);

    int cnt0 = g_cnt[node];
    int cnt = (cnt0 < BCAP) ? cnt0 : BCAP;
    const int2* bkt = g_bucket + (size_t)node * BCAP;

    u64 s2 = 0, q2 = 0;                            // packed (0.0f, 0.0f)
    float mn0 = 3.4e38f, mn1 = 3.4e38f, mx0 = -3.4e38f, mx1 = -3.4e38f;
    float st = 0.f, qt = 0.f, mnt = 3.4e38f, mxt = -3.4e38f;

    int2 o0 = make_int2(0, 0), o1;
    if (cnt > 0) o0 = bkt[0];
    o1 = (cnt > 1) ? bkt[1] : o0;

    for (int p = 0; p < cnt; p += 2) {
        const char* hs0 = ghc + (unsigned)o0.y;
        const char* er0 = eac + (unsigned)o0.x;
        const char* hs1 = ghc + (unsigned)o1.y;
        const char* er1 = eac + (unsigned)o1.x;

        float2 a0 = *(const float2*)(hs0 + moff);
        float2 b0 = *(const float2*)(er0 + moff);
        float ta0 = *(const float*)(hs0 + toff);
        float tb0 = *(const float*)(er0 + toff);
        float2 a1 = *(const float2*)(hs1 + moff);
        float2 b1 = *(const float2*)(er1 + moff);
        float ta1 = *(const float*)(hs1 + toff);
        float tb1 = *(const float*)(er1 + toff);

        int2 n0 = o0, n1 = o1;
        if (p + 2 < cnt) {
            n0 = bkt[p + 2];
            n1 = (p + 3 < cnt) ? bkt[p + 3] : n0;
        }

        // edge p (always valid)
        {
            u64 z2 = add2(add2(hm2, pk2(a0.x, a0.y)), pk2(b0.x, b0.y));
            float z0, z1; upk2(z0, z1, z2);
            float m0 = fmaxf(z0, 0.f), m1 = fmaxf(z1, 0.f);
            u64 m2 = pk2(m0, m1);
            s2 = add2(s2, m2);
            q2 = fma2(m2, m2, q2);
            mn0 = fminf(mn0, z0); mn1 = fminf(mn1, z1);
            mx0 = fmaxf(mx0, z0); mx1 = fmaxf(mx1, z1);
            float zt = htl + ta0 + tb0;
            float mt = fmaxf(zt, 0.f);
            st += mt; qt = fmaf(mt, mt, qt);
            mnt = fminf(mnt, zt); mxt = fmaxf(mxt, zt);
        }
        // edge p+1 (guarded)
        if (p + 1 < cnt) {
            u64 z2 = add2(add2(hm2, pk2(a1.x, a1.y)), pk2(b1.x, b1.y));
            float z0, z1; upk2(z0, z1, z2);
            float m0 = fmaxf(z0, 0.f), m1 = fmaxf(z1, 0.f);
            u64 m2 = pk2(m0, m1);
            s2 = add2(s2, m2);
            q2 = fma2(m2, m2, q2);
            mn0 = fminf(mn0, z0); mn1 = fminf(mn1, z1);
            mx0 = fmaxf(mx0, z0); mx1 = fmaxf(mx1, z1);
            float zt = htl + ta1 + tb1;
            float mt = fmaxf(zt, 0.f);
            st += mt; qt = fmaf(mt, mt, qt);
            mnt = fminf(mnt, zt); mxt = fmaxf(mxt, zt);
        }
        o0 = n0; o1 = n1;
    }

    float cf = (cnt > 0) ? (float)cnt : 1.f;
    float inv = 1.f / cf;
    float sx, sy, qx, qy;
    upk2(sx, sy, s2); upk2(qx, qy, q2);

    // relu(min/max) at the end (exact: relu monotonic)
    float rmn0, rmn1, rmx0, rmx1, rmnt, rmxt;
    if (cnt > 0) {
        rmn0 = fmaxf(mn0, 0.f); rmn1 = fmaxf(mn1, 0.f);
        rmx0 = fmaxf(mx0, 0.f); rmx1 = fmaxf(mx1, 0.f);
        rmnt = fmaxf(mnt, 0.f); rmxt = fmaxf(mxt, 0.f);
    } else {
        rmn0 = rmn1 = rmx0 = rmx1 = rmnt = rmxt = 0.f;
    }

    float mex = sx * inv, mey = sy * inv;
    float sdx = sqrtf(fmaxf(qx * inv - mex * mex, 0.f) + 1e-5f);
    float sdy = sqrtf(fmaxf(qy * inv - mey * mey, 0.f) + 1e-5f);
    float met = st * inv;
    float sdt = sqrtf(fmaxf(qt * inv - met * met, 0.f) + 1e-5f);

    // permuted tf32 stores: logical k = stat*70 + feat -> row offset posk(k)
    float* arow = g_agg + (size_t)node * KDIM;
    int f0 = 2 * lane;
    arow[posk(f0)]       = to_tf32(mex);  arow[posk(f0 + 1)]       = to_tf32(mey);
    arow[posk(70 + f0)]  = to_tf32(rmn0); arow[posk(70 + f0 + 1)]  = to_tf32(rmn1);
    arow[posk(140 + f0)] = to_tf32(rmx0); arow[posk(140 + f0 + 1)] = to_tf32(rmx1);
    arow[posk(210 + f0)] = to_tf32(sdx);  arow[posk(210 + f0 + 1)] = to_tf32(sdy);
    if (lane >= 26) {
        int ft = 64 + (lane - 26);
        arow[posk(ft)]       = to_tf32(met);
        arow[posk(70 + ft)]  = to_tf32(rmnt);
        arow[posk(140 + ft)] = to_tf32(rmxt);
        arow[posk(210 + ft)] = to_tf32(sdt);
    }
    if (lane == 0) g_amp[node] = logf(cf + 1.f) / AVG_LOG_F;
}

// ---------------- TF32 tensor-core GEMM, 4-deep per-stage pipeline ---------
// [64 x 280] @ [280 x 240]; 8 warps 4m x 2n. Each stage buffers B (7680B) and
// its A g-slice (2048B); fill = 3 cp.async/thread; wait_group(2) depth.
#define GM 64
__global__ __launch_bounds__(256, 2)
void gemm_kernel(int layer,
                 const float* __restrict__ b,
                 const float* __restrict__ gamma, const float* __restrict__ beta) {
    __shared__ __align__(16) float4 Stg[4][608];   // per buf: 480 f4 B + 128 f4 A
    int t = threadIdx.x;
    int lane = t & 31, wid = t >> 5;
    int wm = wid & 3, wn = wid >> 2;
    int row0 = blockIdx.x * GM;

    unsigned sb[4] = { smem_u32(&Stg[0][0]), smem_u32(&Stg[1][0]),
                       smem_u32(&Stg[2][0]), smem_u32(&Stg[3][0]) };

    float c[15][4];
#pragma unroll
    for (int i = 0; i < 15; i++)
#pragma unroll
        for (int r = 0; r < 4; r++) c[i][r] = 0.f;

    // A fill addressing: thread t -> f4i = t>>1, hf = t&1; src offset/stage = s*32B
    unsigned a_dst;
    const char* a_src;
    {
        int f4i = t >> 1, hf = t & 1;
        int l = f4i & 3, row8 = (f4i >> 2) & 7, rt = f4i >> 5;
        int r = rt * 16 + row8 + hf * 8;
        a_dst = (unsigned)(7680 + f4i * 16 + hf * 8);
        a_src = (const char*)(g_agg + (size_t)(row0 + r) * KDIM + 2 * l);
    }
    const bool b2nd = (t < 224);
    const char* b_src = (const char*)((const float4*)g_w3 + (size_t)layer * 16800) + (t << 4);
    unsigned b_dst = (unsigned)(t << 4);

#define ISSUE(sv, base) {                                                      \
        const char* bs = b_src + (size_t)(sv) * 7680;                          \
        CP16((base) + b_dst, bs);                                              \
        if (b2nd) CP16((base) + b_dst + 4096, bs + 4096);                      \
        CP8((base) + a_dst, a_src + (sv) * 32);                                \
        CPCOMMIT();                                                            \
    }

    // per-lane fragment offsets
    unsigned aoff  = ((wm * 8 + (lane >> 2)) * 4 + (lane & 3)) * 16 + 7680;
    unsigned boffp = wn * 3584 + (lane >> 2) * 64 + (lane & 3) * 16;
    unsigned bofft = 7168 + wn * 256 + (lane >> 2) * 32 + (lane & 3) * 8;

    // prologue: stages 0..2 in flight
    ISSUE(0, sb[0]); ISSUE(1, sb[1]); ISSUE(2, sb[2]);

    for (int s = 0; s < 35; s++) {
        if (s < 33)      { CPWAIT(2); }
        else if (s == 33){ CPWAIT(1); }
        else             { CPWAIT(0); }
        __syncthreads();

        if (s < 32) ISSUE(s + 3, sb[(s + 3) & 3]);

        unsigned cur = sb[s & 3];
        float4 Av = lds128(cur + aoff);
        unsigned a0 = FU(Av.x), a2 = FU(Av.y), a1 = FU(Av.z), a3 = FU(Av.w);
        unsigned bbase = cur + boffp;
#pragma unroll
        for (int p = 0; p < 7; p++) {
            float4 Bv = lds128(bbase + p * 512);
            mma_tf32(c[2 * p],     a0, a1, a2, a3, FU(Bv.x), FU(Bv.y));
            mma_tf32(c[2 * p + 1], a0, a1, a2, a3, FU(Bv.z), FU(Bv.w));
        }
        float2 Bt = lds64(cur + bofft);
        mma_tf32(c[14], a0, a1, a2, a3, FU(Bt.x), FU(Bt.y));
    }

    // epilogue: combine 3 panels with amp, bias, BN, relu, residual
    int r0 = row0 + wm * 16 + (lane >> 2);
    int r1 = r0 + 8;
    float amp0 = (r0 < N_NODES) ? g_amp[r0] : 1.f;
    float amp1 = (r1 < N_NODES) ? g_amp[r1] : 1.f;
#pragma unroll
    for (int jb = 0; jb < 5; jb++) {
#pragma unroll
        for (int cc = 0; cc < 2; cc++) {
            int j = wn * 40 + jb * 8 + (lane & 3) * 2 + cc;
            if (j < 70) {
                float bj = b[j], gj = gamma[j], btj = beta[j];
                if (r0 < N_NODES) {
                    float comb = c[jb][cc] + amp0 * c[5 + jb][cc] + c[10 + jb][cc] / amp0;
                    float hn = fmaxf((comb + bj) * INV_BN * gj + btj, 0.f);
                    g_h[(size_t)r0 * D + j] += hn;
                }
                if (r1 < N_NODES) {
                    float comb = c[jb][2 + cc] + amp1 * c[5 + jb][2 + cc] + c[10 + jb][2 + cc] / amp1;
                    float hn = fmaxf((comb + bj) * INV_BN * gj + btj, 0.f);
                    g_h[(size_t)r1 * D + j] += hn;
                }
            }
        }
    }
#undef ISSUE
}

// ---------------- global mean pool -----------------------------------------
__global__ void pool_kernel(const int* __restrict__ batch) {
    int n = blockIdx.x * blockDim.y + threadIdx.y;
    int f = threadIdx.x;
    if (n >= N_NODES) return;
    int gi = batch[n];
    atomicAdd(&g_gsum[gi * D + f], g_h[(size_t)n * D + f]);
    if (f == 0) atomicAdd(&g_gcnt[gi], 1.f);
}

// ---------------- final MLP 70->35->17->1 ----------------------------------
__global__ void mlp_kernel(const float* __restrict__ w1, const float* __restrict__ b1,
                           const float* __restrict__ w2, const float* __restrict__ b2,
                           const float* __restrict__ w3, const float* __restrict__ b3,
                           float* __restrict__ out) {
    __shared__ float sg[70], t1[35], t2[17];
    int gi = blockIdx.x;
    int t = threadIdx.x;
    if (t < 70) {
        float cdenom = fmaxf(g_gcnt[gi], 1.f);
        sg[t] = g_gsum[gi * D + t] / cdenom;
    }
    __syncthreads();
    if (t < 35) {
        float s = b1[t];
        for (int k = 0; k < 70; k++) s += sg[k] * w1[k * 35 + t];
        t1[t] = fmaxf(s, 0.f);
    }
    __syncthreads();
    if (t < 17) {
        float s = b2[t];
        for (int k = 0; k < 35; k++) s += t1[k] * w2[k * 17 + t];
        t2[t] = fmaxf(s, 0.f);
    }
    __syncthreads();
    if (t == 0) {
        float s = b3[0];
        for (int k = 0; k < 17; k++) s += t2[k] * w3[k];
        out[gi] = s;
    }
}

// ---------------- launcher --------------------------------------------------
extern "C" void kernel_launch(void* const* d_in, const int* in_sizes, int n_in,
                              void* d_out, int out_size) {
    const int*   x      = (const int*)d_in[0];
    const int*   ei     = (const int*)d_in[1];
    const float* ea     = (const float*)d_in[2];
    const int*   batch  = (const int*)d_in[3];
    const float* emb    = (const float*)d_in[4];
    const float* post_w = (const float*)d_in[5];
    const float* post_b = (const float*)d_in[6];
    const float* gamma  = (const float*)d_in[7];
    const float* beta   = (const float*)d_in[8];
    const float* w1 = (const float*)d_in[9];
    const float* b1 = (const float*)d_in[10];
    const float* w2 = (const float*)d_in[11];
    const float* b2 = (const float*)d_in[12];
    const float* w3 = (const float*)d_in[13];
    const float* b3 = (const float*)d_in[14];
    float* out = (float*)d_out;

    init_kernel<<<(N_NODES + 3) / 4, dim3(70, 4)>>>(x, emb, post_w);   // 1
    scatter_kernel<<<(N_EDGES + 255) / 256, 256>>>(ei);                // 2
    noop_kernel<<<1, 1>>>();                                           // 3 (window shift)

    for (int l = 0; l < 4; l++) {
        agg_kernel<<<(N_NODES * 32 + 255) / 256, 256>>>(ea);           // 4 (l=0) <- profiled
        gemm_kernel<<<NPAD / GM, 256>>>(
            l, post_b + l * 70, gamma + l * 70, beta + l * 70);
    }

    pool_kernel<<<(N_NODES + 3) / 4, dim3(70, 4)>>>(batch);
    mlp_kernel<<<N_GRAPHS, 70>>>(w1, b1, w2, b2, w3, b3, out);
}